// round 12
// baseline (speedup 1.0000x reference)
#include <cuda_runtime.h>
#include <cuda_bf16.h>
#include <cstdint>

// Fused adapter: out = x + 0.1f * ( relu( LN(x) @ Wd + bd ) @ Wu + bu )
// x: [32768, 768] fp32.  Wd: [768,16], Wu: [16,768].
//
// R12 = R11 + the missing up-internal barrier after phase D (fixes the
// x_s overwrite race: stage(s+1) vs residual reads in D(s)).
//  - up warps stage x with LDG.128/STS.128 (24 lanes/warp own float4 chunks)
//  - down warps: 2 d-halves x 4 k-chunks; lane owns 12 d as 3 float4 ->
//    3 LDS.128/row, 4-value convergent butterfly (6 SHFL/row)
//  - LN folded: down_k = rstd*(dot(x,gw_k) - mean*G_k) + C_k

#define D_MODEL  768
#define NROWS    32768
#define NTHREADS 512
#define RB       8
#define GRID     152
#define NBATCH   (NROWS / RB)   // 4096

// named barrier ids (0 reserved for __syncthreads)
#define B_XF0   1   // x_s[buf] staged: up arrives, down syncs (count 512)
#define B_DPF0  3   // dpart[buf] full: down arrives, up syncs (count 512)
#define B_UPI   5   // up-internal (count 256)

#define BAR_SYNC(id, n)   asm volatile("bar.sync %0, %1;"   :: "r"(id), "r"(n) : "memory")
#define BAR_ARRIVE(id, n) asm volatile("bar.arrive %0, %1;" :: "r"(id), "r"(n) : "memory")

// smem layout (floats)
#define OFF_X     0          // 2 * RB*768 = 12288
#define OFF_RED   12288      // 2 * RB*16  = 256
#define OFF_DP    12544      // 2 * RB*16*2 = 512
#define OFF_DNF   13056      // 2 * RB*16  = 256
#define OFF_G     13312      // 16
#define OFF_CB    13328      // 16
#define SMEM_FLOATS 13344
#define SMEM_BYTES  (SMEM_FLOATS * 4)

typedef unsigned long long u64;

__device__ __forceinline__ u64 pk2(float x, float y) {
    u64 r; asm("mov.b64 %0,{%1,%2};" : "=l"(r) : "f"(x), "f"(y)); return r;
}
__device__ __forceinline__ void upk2(u64 v, float& x, float& y) {
    asm("mov.b64 {%0,%1},%2;" : "=f"(x), "=f"(y) : "l"(v));
}
__device__ __forceinline__ u64 ffma2(u64 a, u64 b, u64 c) {
    u64 r; asm("fma.rn.f32x2 %0,%1,%2,%3;" : "=l"(r) : "l"(a), "l"(b), "l"(c)); return r;
}
__device__ __forceinline__ float shx(float v, int off) {
    return __shfl_xor_sync(0xFFFFFFFFu, v, off);
}
// Convergent pair-combine: ONE unconditional shuffle, operands selected first.
__device__ __forceinline__ float bfly(float a, float b, bool hi, int off) {
    const float keep = hi ? b : a;
    const float send = hi ? a : b;
    return keep + shx(send, off);
}

__global__ __launch_bounds__(NTHREADS, 1)
void adapter_fused_kernel(const float* __restrict__ x,
                          const float* __restrict__ ln_g,
                          const float* __restrict__ ln_b,
                          const float* __restrict__ wd,   // [768][16]
                          const float* __restrict__ bd,   // [16]
                          const float* __restrict__ wu,   // [16][768]
                          const float* __restrict__ bu,   // [768]
                          float* __restrict__ out)
{
    extern __shared__ __align__(16) float sm[];
    float* x_s   = sm + OFF_X;     // [2][RB*768]
    float* red_s = sm + OFF_RED;   // [2][RB*16]
    float* dpart = sm + OFF_DP;    // [2][RB*16*2]  (k x 2 d-halves)
    float* dnf   = sm + OFF_DNF;   // [2][RB*16]
    float* G_s   = sm + OFF_G;
    float* Cb_s  = sm + OFF_CB;

    const int t    = threadIdx.x;
    const int lane = t & 31;
    const bool hi16 = (lane & 16) != 0;
    const bool hi8  = (lane & 8)  != 0;
    const bool hi4  = (lane & 4)  != 0;
    const bool hi2  = (lane & 2)  != 0;

    // ===== init: G_k = sum gamma*Wd[:,k], Cb_k = sum beta*Wd[:,k] + bd =====
    if (t < 16) { G_s[t] = 0.0f; Cb_s[t] = bd[t]; }
    __syncthreads();
    if (t < 256) {
        float pg[16], pb[16];
#pragma unroll
        for (int k = 0; k < 16; k++) { pg[k] = 0.0f; pb[k] = 0.0f; }
#pragma unroll
        for (int j = 0; j < 3; j++) {
            const int d = t + 256 * j;
            const float gd = ln_g[d], bdv = ln_b[d];
#pragma unroll
            for (int k = 0; k < 16; k++) {
                const float wv = wd[d * 16 + k];
                pg[k] = fmaf(gd,  wv, pg[k]);
                pb[k] = fmaf(bdv, wv, pb[k]);
            }
        }
#pragma unroll
        for (int which = 0; which < 2; which++) {
            float* v = which ? pb : pg;
            float a8[8], b4[4], c2[2];
#pragma unroll
            for (int j = 0; j < 8; j++) a8[j] = bfly(v[j], v[j + 8], hi16, 16);
#pragma unroll
            for (int j = 0; j < 4; j++) b4[j] = bfly(a8[j], a8[j + 4], hi8, 8);
#pragma unroll
            for (int j = 0; j < 2; j++) c2[j] = bfly(b4[j], b4[j + 2], hi4, 4);
            float z = bfly(c2[0], c2[1], hi2, 2);
            z += shx(z, 1);
            if (!(lane & 1)) {
                if (which) atomicAdd(&Cb_s[lane >> 1], z);
                else       atomicAdd(&G_s[lane >> 1], z);
            }
        }
    }
    __syncthreads();   // G/Cb visible before pipeline starts

    if (t < 256) {
        // ===================== DOWN role (warps 0-7) =====================
        const int w = t >> 5;
        const int h = w & 1;        // d-half: d in [384h, 384h+384)
        const int c = w >> 1;       // k-chunk: k in [4c, 4c+4)
        // gamma-folded weights: lane owns d = 384h + 128i + 4*lane + e
        u64 gw2[3][4][2];
#pragma unroll
        for (int i = 0; i < 3; i++) {
#pragma unroll
            for (int e = 0; e < 4; e++) {
                const int d = 384 * h + 128 * i + 4 * lane + e;
                const float gd = ln_g[d];
#pragma unroll
                for (int p = 0; p < 2; p++) {
                    const float2 v = *reinterpret_cast<const float2*>(wd + d * 16 + 4 * c + 2 * p);
                    gw2[i][e][p] = pk2(gd * v.x, gd * v.y);
                }
            }
        }

        int b = blockIdx.x, s = 0;
        while (b < NBATCH) {
            const int buf = s & 1;
            BAR_SYNC(B_XF0 + buf, NTHREADS);
            const float* xb = x_s + buf * (RB * D_MODEL);
            float* dp = dpart + buf * (RB * 32);
#pragma unroll
            for (int r = 0; r < RB; r++) {
                const float4* xrp = reinterpret_cast<const float4*>(xb + r * D_MODEL + 384 * h) + lane;
                u64 a0 = 0ull, a1 = 0ull;
#pragma unroll
                for (int i = 0; i < 3; i++) {
                    const float4 xv = xrp[32 * i];
                    u64 xx;
                    xx = pk2(xv.x, xv.x);
                    a0 = ffma2(xx, gw2[i][0][0], a0); a1 = ffma2(xx, gw2[i][0][1], a1);
                    xx = pk2(xv.y, xv.y);
                    a0 = ffma2(xx, gw2[i][1][0], a0); a1 = ffma2(xx, gw2[i][1][1], a1);
                    xx = pk2(xv.z, xv.z);
                    a0 = ffma2(xx, gw2[i][2][0], a0); a1 = ffma2(xx, gw2[i][2][1], a1);
                    xx = pk2(xv.w, xv.w);
                    a0 = ffma2(xx, gw2[i][3][0], a0); a1 = ffma2(xx, gw2[i][3][1], a1);
                }
                float v0, v1, v2, v3;
                upk2(a0, v0, v1);   // k = 4c, 4c+1
                upk2(a1, v2, v3);   // k = 4c+2, 4c+3
                // 4-value convergent butterfly (3 SHFL) + 3-SHFL group tree
                const float m0 = bfly(v0, v2, hi16, 16);
                const float m1 = bfly(v1, v3, hi16, 16);
                float z = bfly(m0, m1, hi8, 8);   // 8-lane groups: v0,v1,v2,v3
                z += shx(z, 4);
                z += shx(z, 2);
                z += shx(z, 1);
                if ((lane & 7) == 0)
                    dp[(r * 16 + 4 * c + (lane >> 3)) * 2 + h] = z;
            }
            BAR_ARRIVE(B_DPF0 + buf, NTHREADS);
            b += GRID; s++;
        }
    } else {
        // ====================== UP role (warps 8-15) ======================
        const int tu = t - 256;
        const int cw = tu >> 5;       // 0..7
        // up weights: thread owns cols d = tu + 256j (j<3); all 8 k-pairs
        u64 wu2[3][8];
        float buj[3];
#pragma unroll
        for (int j = 0; j < 3; j++) {
            const int d = tu + 256 * j;
            buj[j] = bu[d];
#pragma unroll
            for (int p = 0; p < 8; p++)
                wu2[j][p] = pk2(wu[(2 * p) * D_MODEL + d], wu[(2 * p + 1) * D_MODEL + d]);
        }

        const bool act = (lane < 24);           // 24 lanes x 8 warps = 192 float4 = 768
        const int  doff = 96 * cw + 4 * lane;   // float offset of this lane's chunk

        int b = blockIdx.x, s = 0;
        float4 xr4[RB];

        auto loadxr = [&](int bb) {
#pragma unroll
            for (int r = 0; r < RB; r++)
                if (act)
                    xr4[r] = *reinterpret_cast<const float4*>(x + (bb * RB + r) * D_MODEL + doff);
        };
        // stage xr4 into buffer `buf` + LN stats
        auto stage = [&](int buf) {
            float* xd = x_s + buf * (RB * D_MODEL);
            float* rd = red_s + buf * (RB * 16);
#pragma unroll
            for (int r = 0; r < RB; r++) {
                const float4 v = xr4[r];
                float ss = 0.0f, qq = 0.0f;
                if (act) {
                    *reinterpret_cast<float4*>(xd + r * D_MODEL + doff) = v;
                    ss = (v.x + v.y) + (v.z + v.w);
                    qq = fmaf(v.x, v.x, fmaf(v.y, v.y, fmaf(v.z, v.z, v.w * v.w)));
                }
                float m = bfly(ss, qq, hi16, 16);
                m += shx(m, 8); m += shx(m, 4); m += shx(m, 2); m += shx(m, 1);
                if ((lane & 15) == 0)
                    rd[r * 16 + 2 * cw + (lane >> 4)] = m;
            }
        };

        // prologue
        loadxr(b);
        stage(0);
        BAR_ARRIVE(B_XF0, NTHREADS);
        if (b + GRID < NBATCH) loadxr(b + GRID);

        while (b < NBATCH) {
            const int bn   = b + GRID;
            const int bufc = s & 1;
            const int bufn = bufc ^ 1;

            if (bn < NBATCH) {
                stage(bufn);
                BAR_ARRIVE(B_XF0 + bufn, NTHREADS);
                if (bn + GRID < NBATCH) loadxr(bn + GRID);
            }

            BAR_SYNC(B_DPF0 + bufc, NTHREADS);      // dpart[bufc] ready

            // -- C: warp cw = row cw; finalize stats + combine + relu --
            {
                const float* rd = red_s + bufc * (RB * 16);
                const float4* rp = reinterpret_cast<const float4*>(rd + cw * 16);
                const float4 f0 = rp[0], f1 = rp[1], f2 = rp[2], f3 = rp[3];
                const float ss = ((f0.x + f0.z) + (f1.x + f1.z)) + ((f2.x + f2.z) + (f3.x + f3.z));
                const float qq = ((f0.y + f0.w) + (f1.y + f1.w)) + ((f2.y + f2.w) + (f3.y + f3.w));
                const float mean = ss * (1.0f / D_MODEL);
                const float var  = qq * (1.0f / D_MODEL) - mean * mean;
                const float rstd = rsqrtf(var + 1e-5f);
                if (lane < 16) {
                    const float2 pd = reinterpret_cast<const float2*>(dpart + bufc * (RB * 32))[cw * 16 + lane];
                    const float P = pd.x + pd.y;
                    const float dv = rstd * (P - mean * G_s[lane]) + Cb_s[lane];
                    dnf[bufc * (RB * 16) + cw * 16 + lane] = fmaxf(dv, 0.0f);
                }
            }
            BAR_SYNC(B_UPI, 256);                   // dnf[bufc] visible to up warps

            // -- D: up-proj + scale + residual (from x_s[bufc]) + store --
            {
                const float* df = dnf + bufc * (RB * 16);
                const float* xb = x_s + bufc * (RB * D_MODEL);
                const int rbase = b * RB;
#pragma unroll
                for (int r = 0; r < RB; r++) {
                    const float4 d0 = reinterpret_cast<const float4*>(df)[r * 4 + 0];
                    const float4 d1 = reinterpret_cast<const float4*>(df)[r * 4 + 1];
                    const float4 d2 = reinterpret_cast<const float4*>(df)[r * 4 + 2];
                    const float4 d3 = reinterpret_cast<const float4*>(df)[r * 4 + 3];
                    u64 dn[8];
                    dn[0] = pk2(d0.x, d0.y); dn[1] = pk2(d0.z, d0.w);
                    dn[2] = pk2(d1.x, d1.y); dn[3] = pk2(d1.z, d1.w);
                    dn[4] = pk2(d2.x, d2.y); dn[5] = pk2(d2.z, d2.w);
                    dn[6] = pk2(d3.x, d3.y); dn[7] = pk2(d3.z, d3.w);
#pragma unroll
                    for (int j = 0; j < 3; j++) {
                        u64 u0 = 0ull, u1 = 0ull;
#pragma unroll
                        for (int p = 0; p < 8; p += 2) {
                            u0 = ffma2(dn[p],     wu2[j][p],     u0);
                            u1 = ffma2(dn[p + 1], wu2[j][p + 1], u1);
                        }
                        float f0, f1, f2, f3;
                        upk2(u0, f0, f1); upk2(u1, f2, f3);
                        const float up = (f0 + f1) + (f2 + f3);
                        const float res = xb[r * D_MODEL + tu + 256 * j];
                        out[(rbase + r) * D_MODEL + tu + 256 * j] = fmaf(0.1f, up + buj[j], res);
                    }
                }
            }

            // RACE FIX: all up warps must finish D (residual reads of
            // x_s[bufc] and red_s consumption) before any warp's next-iter
            // stage() overwrites those buffers.
            BAR_SYNC(B_UPI, 256);

            b = bn; s++;
        }
    }
}

extern "C" void kernel_launch(void* const* d_in, const int* in_sizes, int n_in,
                              void* d_out, int out_size)
{
    const float* x    = (const float*)d_in[0];
    const float* ln_g = (const float*)d_in[1];
    const float* ln_b = (const float*)d_in[2];
    const float* wd   = (const float*)d_in[3];
    const float* bd   = (const float*)d_in[4];
    const float* wu   = (const float*)d_in[5];
    const float* bu   = (const float*)d_in[6];
    float* out = (float*)d_out;

    cudaFuncSetAttribute(adapter_fused_kernel,
                         cudaFuncAttributeMaxDynamicSharedMemorySize, SMEM_BYTES);
    adapter_fused_kernel<<<GRID, NTHREADS, SMEM_BYTES>>>(x, ln_g, ln_b, wd, bd, wu, bu, out);
}

// round 13
// speedup vs baseline: 1.1357x; 1.1357x over previous
#include <cuda_runtime.h>
#include <cuda_bf16.h>
#include <cstdint>

// Fused adapter: out = x + 0.1f * ( relu( LN(x) @ Wd + bd ) @ Wu + bu )
// x: [32768, 768] fp32.  Wd: [768,16], Wu: [16,768].
//
// R13: NO x staging. Down warps load x straight into registers (coalesced
// LDG matching their weight layout) and compute LN partials + folded
// down-proj. Up warps re-read the residual from global (L1-hot) and do
// stats-finalize/combine/relu + up-proj + store. Smem = tiny ring buffers
// (red_s/dpart/dnf) only. One barrier wait per role per batch.
// LN folded (R6): down_k = rstd*(dot(x, gamma.*Wd_k) - mean*G_k) + C_k.

#define D_MODEL  768
#define NROWS    32768
#define NTHREADS 512
#define RB       8
#define GRID     152
#define NBATCH   (NROWS / RB)   // 4096

// named barrier ids (0 reserved for __syncthreads)
#define B_DPF0  1   // red_s/dpart[buf] full: down arrives, up syncs (512)
#define B_EMP0  3   // red_s/dpart[buf] consumed: up arrives, down syncs (512)
#define B_UPI   5   // up-internal: dnf visible (256)

#define BAR_SYNC(id, n)   asm volatile("bar.sync %0, %1;"   :: "r"(id), "r"(n) : "memory")
#define BAR_ARRIVE(id, n) asm volatile("bar.arrive %0, %1;" :: "r"(id), "r"(n) : "memory")

typedef unsigned long long u64;

__device__ __forceinline__ u64 pk2(float x, float y) {
    u64 r; asm("mov.b64 %0,{%1,%2};" : "=l"(r) : "f"(x), "f"(y)); return r;
}
__device__ __forceinline__ void upk2(u64 v, float& x, float& y) {
    asm("mov.b64 {%0,%1},%2;" : "=f"(x), "=f"(y) : "l"(v));
}
__device__ __forceinline__ u64 ffma2(u64 a, u64 b, u64 c) {
    u64 r; asm("fma.rn.f32x2 %0,%1,%2,%3;" : "=l"(r) : "l"(a), "l"(b), "l"(c)); return r;
}
__device__ __forceinline__ float shx(float v, int off) {
    return __shfl_xor_sync(0xFFFFFFFFu, v, off);
}
// Convergent pair-combine: ONE unconditional shuffle, operands selected first.
__device__ __forceinline__ float bfly(float a, float b, bool hi, int off) {
    const float keep = hi ? b : a;
    const float send = hi ? a : b;
    return keep + shx(send, off);
}

__global__ __launch_bounds__(NTHREADS, 1)
void adapter_fused_kernel(const float* __restrict__ x,
                          const float* __restrict__ ln_g,
                          const float* __restrict__ ln_b,
                          const float* __restrict__ wd,   // [768][16]
                          const float* __restrict__ bd,   // [16]
                          const float* __restrict__ wu,   // [16][768]
                          const float* __restrict__ bu,   // [768]
                          float* __restrict__ out)
{
    __shared__ __align__(16) float red_s[2][RB * 8];    // [buf][row*8 + 2g + e]
    __shared__ __align__(16) float dpart[2][RB * 64];   // [buf][(row*16+k)*4 + g]
    __shared__ __align__(16) float dnf[2][RB * 16];     // [buf][row*16 + k]
    __shared__ __align__(16) float G_s[16];
    __shared__ __align__(16) float Cb_s[16];

    const int t    = threadIdx.x;
    const int lane = t & 31;
    const bool hi16 = (lane & 16) != 0;
    const bool hi8  = (lane & 8)  != 0;
    const bool hi4  = (lane & 4)  != 0;
    const bool hi2  = (lane & 2)  != 0;

    // ===== init: G_k = sum gamma*Wd[:,k], Cb_k = sum beta*Wd[:,k] + bd =====
    if (t < 16) { G_s[t] = 0.0f; Cb_s[t] = bd[t]; }
    __syncthreads();
    if (t < 256) {
        float pg[16], pb[16];
#pragma unroll
        for (int k = 0; k < 16; k++) { pg[k] = 0.0f; pb[k] = 0.0f; }
#pragma unroll
        for (int j = 0; j < 3; j++) {
            const int d = t + 256 * j;
            const float gd = ln_g[d], bdv = ln_b[d];
#pragma unroll
            for (int k = 0; k < 16; k++) {
                const float wv = wd[d * 16 + k];
                pg[k] = fmaf(gd,  wv, pg[k]);
                pb[k] = fmaf(bdv, wv, pb[k]);
            }
        }
#pragma unroll
        for (int which = 0; which < 2; which++) {
            float* v = which ? pb : pg;
            float a8[8], b4[4], c2[2];
#pragma unroll
            for (int j = 0; j < 8; j++) a8[j] = bfly(v[j], v[j + 8], hi16, 16);
#pragma unroll
            for (int j = 0; j < 4; j++) b4[j] = bfly(a8[j], a8[j + 4], hi8, 8);
#pragma unroll
            for (int j = 0; j < 2; j++) c2[j] = bfly(b4[j], b4[j + 2], hi4, 4);
            float z = bfly(c2[0], c2[1], hi2, 2);
            z += shx(z, 1);
            if (!(lane & 1)) {
                if (which) atomicAdd(&Cb_s[lane >> 1], z);
                else       atomicAdd(&G_s[lane >> 1], z);
            }
        }
    }
    __syncthreads();   // G/Cb visible to all (up side consumes them)

    if (t < 256) {
        // ===================== DOWN role (warps 0-7) =====================
        const int w = t >> 5;
        const int c = w & 1;        // k-chunk: k in [8c, 8c+8)
        const int g = w >> 1;       // d-group: d in [192g, 192g+192)
        // gamma-folded weights: lane owns d = 192g + 32i + lane (i<6)
        u64 gw2[6][4];
#pragma unroll
        for (int i = 0; i < 6; i++) {
            const int d = 192 * g + 32 * i + lane;
            const float gd = ln_g[d];
#pragma unroll
            for (int p = 0; p < 4; p++) {
                const float2 v = *reinterpret_cast<const float2*>(wd + d * 16 + 8 * c + 2 * p);
                gw2[i][p] = pk2(gd * v.x, gd * v.y);
            }
        }

        int b = blockIdx.x, s = 0;
        float xc[RB][6];   // this warp's x slice, 48 regs
        const int xoff = 192 * g + lane;
        {
            const int rbase = b * RB;
#pragma unroll
            for (int r = 0; r < RB; r++)
#pragma unroll
                for (int i = 0; i < 6; i++)
                    xc[r][i] = x[(rbase + r) * D_MODEL + xoff + 32 * i];
        }

        while (b < NBATCH) {
            const int buf = s & 1;
            if (s >= 2) BAR_SYNC(B_EMP0 + buf, NTHREADS);   // ring slot free

            // -- LN partial stats over this 192-d group (c==0 warps only;
            //    the c==1 twin holds identical x) --
            if (c == 0) {
#pragma unroll
                for (int r = 0; r < RB; r++) {
                    float ss = ((xc[r][0] + xc[r][1]) + (xc[r][2] + xc[r][3]))
                             + (xc[r][4] + xc[r][5]);
                    float qq = fmaf(xc[r][0], xc[r][0], fmaf(xc[r][1], xc[r][1],
                               fmaf(xc[r][2], xc[r][2], fmaf(xc[r][3], xc[r][3],
                               fmaf(xc[r][4], xc[r][4], xc[r][5] * xc[r][5])))));
                    float m = bfly(ss, qq, hi16, 16);   // lanes 0-15: s, 16-31: q
                    m += shx(m, 8); m += shx(m, 4); m += shx(m, 2); m += shx(m, 1);
                    if ((lane & 15) == 0)
                        red_s[buf][r * 8 + 2 * g + (lane >> 4)] = m;
                }
            }

            // -- folded down-proj from registers; 9-SHFL butterfly --
#pragma unroll
            for (int r = 0; r < RB; r++) {
                u64 a0 = 0ull, a1 = 0ull, a2 = 0ull, a3 = 0ull;
#pragma unroll
                for (int i = 0; i < 6; i++) {
                    const u64 xx = pk2(xc[r][i], xc[r][i]);
                    a0 = ffma2(xx, gw2[i][0], a0);
                    a1 = ffma2(xx, gw2[i][1], a1);
                    a2 = ffma2(xx, gw2[i][2], a2);
                    a3 = ffma2(xx, gw2[i][3], a3);
                }
                float v0, v1, v2, v3, v4, v5, v6, v7;
                upk2(a0, v0, v1); upk2(a1, v2, v3); upk2(a2, v4, v5); upk2(a3, v6, v7);
                const float w0 = bfly(v0, v4, hi16, 16);
                const float w1 = bfly(v1, v5, hi16, 16);
                const float w2 = bfly(v2, v6, hi16, 16);
                const float w3 = bfly(v3, v7, hi16, 16);
                const float u0 = bfly(w0, w2, hi8, 8);
                const float u1 = bfly(w1, w3, hi8, 8);
                float z = bfly(u0, u1, hi4, 4);
                z += shx(z, 2);
                z += shx(z, 1);
                if ((lane & 3) == 0)
                    dpart[buf][(r * 16 + 8 * c + (lane >> 2)) * 4 + g] = z;
            }
            BAR_ARRIVE(B_DPF0 + buf, NTHREADS);

            // prefetch next batch into xc (latency hidden by next EMP wait)
            b += GRID; s++;
            if (b < NBATCH) {
                const int rbase = b * RB;
#pragma unroll
                for (int r = 0; r < RB; r++)
#pragma unroll
                    for (int i = 0; i < 6; i++)
                        xc[r][i] = x[(rbase + r) * D_MODEL + xoff + 32 * i];
            }
        }
    } else {
        // ====================== UP role (warps 8-15) ======================
        const int tu = t - 256;
        const int cw = tu >> 5;       // 0..7 -> combine row
        // up weights: thread owns cols d = tu + 256j (j<3); all 8 k-pairs
        u64 wu2[3][8];
        float buj[3];
#pragma unroll
        for (int j = 0; j < 3; j++) {
            const int d = tu + 256 * j;
            buj[j] = bu[d];
#pragma unroll
            for (int p = 0; p < 8; p++)
                wu2[j][p] = pk2(wu[(2 * p) * D_MODEL + d], wu[(2 * p + 1) * D_MODEL + d]);
        }

        int b = blockIdx.x, s = 0;
        float xr[RB][3];   // residual (global re-read; L1-hot)
        {
            const int rbase = b * RB;
#pragma unroll
            for (int r = 0; r < RB; r++)
#pragma unroll
                for (int j = 0; j < 3; j++)
                    xr[r][j] = x[(rbase + r) * D_MODEL + tu + 256 * j];
        }

        while (b < NBATCH) {
            const int bufc = s & 1;
            BAR_SYNC(B_DPF0 + bufc, NTHREADS);     // red_s/dpart[bufc] ready

            // -- C: warp cw = row cw; finalize stats + combine + relu --
            {
                float v = (lane < 8) ? red_s[bufc][cw * 8 + lane] : 0.0f;
                // even lanes: s partials (4 groups), odd lanes: q partials
                v += shx(v, 2);
                v += shx(v, 4);
                const float s_tot = __shfl_sync(0xFFFFFFFFu, v, 0);
                const float q_tot = __shfl_sync(0xFFFFFFFFu, v, 1);
                const float mean = s_tot * (1.0f / D_MODEL);
                const float var  = q_tot * (1.0f / D_MODEL) - mean * mean;
                const float rstd = rsqrtf(var + 1e-5f);
                if (lane < 16) {
                    const float4 p4 = reinterpret_cast<const float4*>(dpart[bufc])[cw * 16 + lane];
                    const float P = (p4.x + p4.y) + (p4.z + p4.w);
                    const float dv = rstd * (P - mean * G_s[lane]) + Cb_s[lane];
                    dnf[bufc][cw * 16 + lane] = fmaxf(dv, 0.0f);
                }
            }
            BAR_ARRIVE(B_EMP0 + bufc, NTHREADS);   // red_s/dpart[bufc] consumed
            BAR_SYNC(B_UPI, 256);                  // dnf[bufc] visible to up warps

            // -- D: up-proj + scale + residual + store --
            {
                const float* df = dnf[bufc];
                const int rbase = b * RB;
#pragma unroll
                for (int r = 0; r < RB; r++) {
                    const float4 d0 = reinterpret_cast<const float4*>(df)[r * 4 + 0];
                    const float4 d1 = reinterpret_cast<const float4*>(df)[r * 4 + 1];
                    const float4 d2 = reinterpret_cast<const float4*>(df)[r * 4 + 2];
                    const float4 d3 = reinterpret_cast<const float4*>(df)[r * 4 + 3];
                    u64 dn[8];
                    dn[0] = pk2(d0.x, d0.y); dn[1] = pk2(d0.z, d0.w);
                    dn[2] = pk2(d1.x, d1.y); dn[3] = pk2(d1.z, d1.w);
                    dn[4] = pk2(d2.x, d2.y); dn[5] = pk2(d2.z, d2.w);
                    dn[6] = pk2(d3.x, d3.y); dn[7] = pk2(d3.z, d3.w);
#pragma unroll
                    for (int j = 0; j < 3; j++) {
                        u64 u0 = 0ull, u1 = 0ull;
#pragma unroll
                        for (int p = 0; p < 8; p += 2) {
                            u0 = ffma2(dn[p],     wu2[j][p],     u0);
                            u1 = ffma2(dn[p + 1], wu2[j][p + 1], u1);
                        }
                        float f0, f1, f2, f3;
                        upk2(u0, f0, f1); upk2(u1, f2, f3);
                        const float up = (f0 + f1) + (f2 + f3);
                        out[(rbase + r) * D_MODEL + tu + 256 * j] = fmaf(0.1f, up + buj[j], xr[r][j]);
                    }
                }
            }

            // prefetch next residual (latency hidden by next DPF wait)
            b += GRID; s++;
            if (b < NBATCH) {
                const int rbase = b * RB;
#pragma unroll
                for (int r = 0; r < RB; r++)
#pragma unroll
                    for (int j = 0; j < 3; j++)
                        xr[r][j] = x[(rbase + r) * D_MODEL + tu + 256 * j];
            }
        }
    }
}

extern "C" void kernel_launch(void* const* d_in, const int* in_sizes, int n_in,
                              void* d_out, int out_size)
{
    const float* x    = (const float*)d_in[0];
    const float* ln_g = (const float*)d_in[1];
    const float* ln_b = (const float*)d_in[2];
    const float* wd   = (const float*)d_in[3];
    const float* bd   = (const float*)d_in[4];
    const float* wu   = (const float*)d_in[5];
    const float* bu   = (const float*)d_in[6];
    float* out = (float*)d_out;

    adapter_fused_kernel<<<GRID, NTHREADS>>>(x, ln_g, ln_b, wd, bd, wu, bu, out);
}

// round 14
// speedup vs baseline: 1.1418x; 1.0053x over previous
#include <cuda_runtime.h>
#include <cstdint>

// Fused adapter: out = x + 0.1f * ( relu( LN(x) @ Wd + bd ) @ Wu + bu )
// x: [32768, 768] fp32.  Wd: [768,16], Wu: [16,768].
//
// R14: both GEMMs on tensor cores (mma.sync.m16n8k8 tf32), RB=16.
//  down warps (0-7): prefetch+stage x (fp32, row pad 772) + LN stats,
//    then kslice-w MMA: C[16x16] partial over k=96w..96w+95 -> dpart.
//  up warps (8-15): combine 8 partials + folded-LN correction + relu ->
//    dnf (A-fragment order), then up MMA over 12 n-tiles each + epilogue
//    (bias, x0.1, residual from x_s, STG.64).
//  Weights pre-swizzled to B-fragment order in smem at init (gamma folded
//  into Wd, cvt.rna tf32). LN folded: down_k = rstd*(dot-mean*G_k)+Cb_k.

#define D_MODEL  768
#define NROWS    32768
#define NTHREADS 512
#define RB       16
#define GRID     152
#define NBATCH   (NROWS / RB)   // 2048

#define XS_STRIDE 772           // 768 + 4 pad: conflict-free A-fragment LDS
#define XS_BUF    (RB * XS_STRIDE)

// smem float offsets
#define OFF_XS   0                      // 2 * 12352 = 24704
#define OFF_WDF  24704                  // 192 frags * 64 = 12288 (tf32 bits)
#define OFF_WUF  36992                  // 12288
#define OFF_DP   49280                  // 2 * (8ks*2nt*32*4) = 4096
#define OFF_DNF  53376                  // 2 * 256 = 512
#define OFF_STT  53888                  // 2 * 16 rows * float2 = 64
#define OFF_G    53952                  // 16
#define OFF_CB   53968                  // 16
#define OFF_BU   53984                  // 768
#define SMEM_FLOATS 54752
#define SMEM_BYTES  (SMEM_FLOATS * 4)   // 219008 B

// named barrier ids
#define B_DPF0  1   // dpart/stats full: down arrives, up syncs (512)
#define B_EMP0  3   // batch fully consumed: up arrives, down syncs (512)
#define B_DWNI  5   // down-internal: x_s staged before MMA (256)
#define B_UPI   6   // up-internal: dnf ready before up-MMA (256)

#define BAR_SYNC(id, n)   asm volatile("bar.sync %0, %1;"   :: "r"(id), "r"(n) : "memory")
#define BAR_ARRIVE(id, n) asm volatile("bar.arrive %0, %1;" :: "r"(id), "r"(n) : "memory")

__device__ __forceinline__ float shx(float v, int off) {
    return __shfl_xor_sync(0xFFFFFFFFu, v, off);
}
__device__ __forceinline__ float bfly(float a, float b, bool hi, int off) {
    const float keep = hi ? b : a;
    const float send = hi ? a : b;
    return keep + shx(send, off);
}
__device__ __forceinline__ uint32_t f2tf(float f) {
    uint32_t r; asm("cvt.rna.tf32.f32 %0, %1;" : "=r"(r) : "f"(f)); return r;
}
__device__ __forceinline__ void mma8(float& d0, float& d1, float& d2, float& d3,
                                     uint32_t a0, uint32_t a1, uint32_t a2, uint32_t a3,
                                     uint32_t b0, uint32_t b1) {
    asm volatile(
        "mma.sync.aligned.m16n8k8.row.col.f32.tf32.tf32.f32 "
        "{%0,%1,%2,%3}, {%4,%5,%6,%7}, {%8,%9}, {%0,%1,%2,%3};"
        : "+f"(d0), "+f"(d1), "+f"(d2), "+f"(d3)
        : "r"(a0), "r"(a1), "r"(a2), "r"(a3), "r"(b0), "r"(b1));
}

__global__ __launch_bounds__(NTHREADS, 1)
void adapter_fused_kernel(const float* __restrict__ x,
                          const float* __restrict__ ln_g,
                          const float* __restrict__ ln_b,
                          const float* __restrict__ wd,   // [768][16]
                          const float* __restrict__ bd,   // [16]
                          const float* __restrict__ wu,   // [16][768]
                          const float* __restrict__ bu,   // [768]
                          float* __restrict__ out)
{
    extern __shared__ __align__(16) float smp[];

    const int t    = threadIdx.x;
    const int lane = t & 31;
    const int wid  = t >> 5;
    const bool hi16 = (lane & 16) != 0;
    const bool hi8  = (lane & 8)  != 0;
    const bool hi4  = (lane & 4)  != 0;
    const bool hi2  = (lane & 2)  != 0;

    // ===================== init (once per block) =====================
    if (t < 16) { smp[OFF_G + t] = 0.0f; smp[OFF_CB + t] = bd[t]; }
    __syncthreads();

    // G_k = sum gamma*Wd[:,k] ; Cb_k = sum beta*Wd[:,k] + bd  (fp32, 256 thr)
    if (t < 256) {
        float pg[16], pb[16];
#pragma unroll
        for (int k = 0; k < 16; k++) { pg[k] = 0.0f; pb[k] = 0.0f; }
#pragma unroll
        for (int j = 0; j < 3; j++) {
            const int d = t + 256 * j;
            const float gd = ln_g[d], bdv = ln_b[d];
#pragma unroll
            for (int k = 0; k < 16; k++) {
                const float wv = wd[d * 16 + k];
                pg[k] = fmaf(gd,  wv, pg[k]);
                pb[k] = fmaf(bdv, wv, pb[k]);
            }
        }
#pragma unroll
        for (int which = 0; which < 2; which++) {
            float* v = which ? pb : pg;
            float a8[8], b4[4], c2[2];
#pragma unroll
            for (int j = 0; j < 8; j++) a8[j] = bfly(v[j], v[j + 8], hi16, 16);
#pragma unroll
            for (int j = 0; j < 4; j++) b4[j] = bfly(a8[j], a8[j + 4], hi8, 8);
#pragma unroll
            for (int j = 0; j < 2; j++) c2[j] = bfly(b4[j], b4[j + 2], hi4, 4);
            float z = bfly(c2[0], c2[1], hi2, 2);
            z += shx(z, 1);
            if (!(lane & 1)) {
                if (which) atomicAdd(&smp[OFF_CB + (lane >> 1)], z);
                else       atomicAdd(&smp[OFF_G  + (lane >> 1)], z);
            }
        }
    }

    // B-fragment swizzle: gamma-folded Wd (down) + Wu (up), cvt to tf32.
    {
        uint32_t* wdfw = reinterpret_cast<uint32_t*>(smp + OFF_WDF);
        uint32_t* wufw = reinterpret_cast<uint32_t*>(smp + OFF_WUF);
        for (int fi = wid; fi < 192; fi += 16) {
            {   // down B: GW[768(k) x 16(n)]: frag fi = kstep*2 + ntile
                const int s = fi >> 1, nt = fi & 1;
                const int d0 = 8 * s + (lane & 3), d1 = d0 + 4;
                const int kb = 8 * nt + (lane >> 2);
                wdfw[fi * 64 + 2 * lane]     = f2tf(ln_g[d0] * wd[d0 * 16 + kb]);
                wdfw[fi * 64 + 2 * lane + 1] = f2tf(ln_g[d1] * wd[d1 * 16 + kb]);
            }
            {   // up B: WU[16(k) x 768(n)]: frag fi = kstep*96 + ntile
                const int s = fi / 96, nt = fi % 96;
                const int k0 = 8 * s + (lane & 3), k1 = k0 + 4;
                const int d = 8 * nt + (lane >> 2);
                wufw[fi * 64 + 2 * lane]     = f2tf(wu[k0 * D_MODEL + d]);
                wufw[fi * 64 + 2 * lane + 1] = f2tf(wu[k1 * D_MODEL + d]);
            }
        }
    }
    for (int d = t; d < D_MODEL; d += NTHREADS) smp[OFF_BU + d] = bu[d];
    __syncthreads();

    if (t < 256) {
        // ===================== DOWN role (warps 0-7) =====================
        const int w = wid;                  // kslice w: ksteps 12w..12w+11
        float4 xc4[2][6];                   // rows 2w, 2w+1 of the batch

        auto pref = [&](int bb) {
#pragma unroll
            for (int rr = 0; rr < 2; rr++) {
                const float4* xp = reinterpret_cast<const float4*>(
                    x + (bb * RB + 2 * w + rr) * D_MODEL);
#pragma unroll
                for (int i = 0; i < 6; i++) xc4[rr][i] = xp[lane + 32 * i];
            }
        };

        int b = blockIdx.x, s = 0;
        pref(b);

        while (b < NBATCH) {
            const int buf = s & 1;
            if (s >= 2) BAR_SYNC(B_EMP0 + buf, NTHREADS);

            // -- stage x (fp32) + per-row LN stats --
#pragma unroll
            for (int rr = 0; rr < 2; rr++) {
                const int row = 2 * w + rr;
                float* xd = smp + OFF_XS + buf * XS_BUF + row * XS_STRIDE;
                float ss = 0.0f, qq = 0.0f;
#pragma unroll
                for (int i = 0; i < 6; i++) {
                    const float4 v = xc4[rr][i];
                    *reinterpret_cast<float4*>(xd + 4 * (lane + 32 * i)) = v;
                    ss += (v.x + v.y) + (v.z + v.w);
                    qq = fmaf(v.x, v.x, fmaf(v.y, v.y,
                         fmaf(v.z, v.z, fmaf(v.w, v.w, qq))));
                }
                float m = bfly(ss, qq, hi16, 16);
                m += shx(m, 8); m += shx(m, 4); m += shx(m, 2); m += shx(m, 1);
                const float q0 = shx(m, 16);
                if (lane == 0) {
                    const float mean = m * (1.0f / D_MODEL);
                    const float var  = q0 * (1.0f / D_MODEL) - mean * mean;
                    *reinterpret_cast<float2*>(smp + OFF_STT + buf * 32 + row * 2)
                        = make_float2(mean, rsqrtf(var + 1e-5f));
                }
            }
            const int bn = b + GRID;
            if (bn < NBATCH) pref(bn);      // LDG latency hidden by barrier+MMA
            BAR_SYNC(B_DWNI, 256);          // all of x_s[buf] staged

            // -- down MMA: kslice w, both n-tiles --
            {
                const float* xsb = smp + OFF_XS + buf * XS_BUF;
                const uint32_t* wdfw = reinterpret_cast<const uint32_t*>(smp + OFF_WDF);
                const float* a00 = xsb + (lane >> 2) * XS_STRIDE + (lane & 3);
                const float* a10 = a00 + 8 * XS_STRIDE;
                float c00 = 0, c01 = 0, c02 = 0, c03 = 0;
                float c10 = 0, c11 = 0, c12 = 0, c13 = 0;
#pragma unroll
                for (int i = 0; i < 12; i++) {
                    const int ks = w * 12 + i;
                    const uint32_t A0 = __float_as_uint(a00[8 * ks]);
                    const uint32_t A2 = __float_as_uint(a00[8 * ks + 4]);
                    const uint32_t A1 = __float_as_uint(a10[8 * ks]);
                    const uint32_t A3 = __float_as_uint(a10[8 * ks + 4]);
                    const uint2 b0 = *reinterpret_cast<const uint2*>(
                        wdfw + (ks * 2 + 0) * 64 + 2 * lane);
                    const uint2 b1 = *reinterpret_cast<const uint2*>(
                        wdfw + (ks * 2 + 1) * 64 + 2 * lane);
                    mma8(c00, c01, c02, c03, A0, A1, A2, A3, b0.x, b0.y);
                    mma8(c10, c11, c12, c13, A0, A1, A2, A3, b1.x, b1.y);
                }
                float* dpb = smp + OFF_DP + buf * 2048;
                *reinterpret_cast<float4*>(dpb + (w * 2 + 0) * 128 + lane * 4)
                    = make_float4(c00, c01, c02, c03);
                *reinterpret_cast<float4*>(dpb + (w * 2 + 1) * 128 + lane * 4)
                    = make_float4(c10, c11, c12, c13);
            }
            BAR_ARRIVE(B_DPF0 + buf, NTHREADS);
            b = bn; s++;
        }
    } else {
        // ====================== UP role (warps 8-15) ======================
        const int tu = t - 256;
        const int wq = tu >> 5;             // 0..7: n-tile group

        int b = blockIdx.x, s = 0;
        while (b < NBATCH) {
            const int bufc = s & 1;
            BAR_SYNC(B_DPF0 + bufc, NTHREADS);   // dpart/stats[bufc] ready

            // -- C: combine 8 k-slice partials + LN correction + relu ->
            //       dnf in up-A-fragment order. Element e = tu: (r, cB). --
            {
                const int r = tu >> 4, cB = tu & 15;
                const float2 st = *reinterpret_cast<const float2*>(
                    smp + OFF_STT + bufc * 32 + r * 2);
                const int tidf = (r & 7) * 4 + ((cB & 7) >> 1);
                const int reg  = (cB & 1) + 2 * (r >> 3);
                const float* dpb = smp + OFF_DP + bufc * 2048
                                 + (cB >> 3) * 128 + tidf * 4 + reg;
                float P = 0.0f;
#pragma unroll
                for (int ks = 0; ks < 8; ks++) P += dpb[ks * 256];
                float dv = st.y * (P - st.x * smp[OFF_G + cB]) + smp[OFF_CB + cB];
                dv = fmaxf(dv, 0.0f);
                const int sU = cB >> 3;
                const int tA = (r & 7) * 4 + (cB & 3);
                const int j  = (r >> 3) + 2 * ((cB >> 2) & 1);
                smp[OFF_DNF + bufc * 256 + sU * 128 + tA * 4 + j] = dv;
            }
            BAR_SYNC(B_UPI, 256);                // dnf[bufc] complete

            // -- D: up MMA over 12 n-tiles + epilogue --
            {
                const uint32_t* wufw = reinterpret_cast<const uint32_t*>(smp + OFF_WUF);
                const uint4 A0 = *reinterpret_cast<const uint4*>(
                    smp + OFF_DNF + bufc * 256 + lane * 4);
                const uint4 A1 = *reinterpret_cast<const uint4*>(
                    smp + OFF_DNF + bufc * 256 + 128 + lane * 4);
                const float* xsb = smp + OFF_XS + bufc * XS_BUF;
                const int rr0 = lane >> 2, rr1 = rr0 + 8;
                const int cc  = (lane & 3) * 2;
                const int rbase = b * RB;
#pragma unroll
                for (int i = 0; i < 12; i++) {
                    const int nt = wq * 12 + i;
                    const uint2 B0 = *reinterpret_cast<const uint2*>(
                        wufw + nt * 64 + 2 * lane);
                    const uint2 B1 = *reinterpret_cast<const uint2*>(
                        wufw + (96 + nt) * 64 + 2 * lane);
                    float c0 = 0, c1 = 0, c2 = 0, c3 = 0;
                    mma8(c0, c1, c2, c3, A0.x, A0.y, A0.z, A0.w, B0.x, B0.y);
                    mma8(c0, c1, c2, c3, A1.x, A1.y, A1.z, A1.w, B1.x, B1.y);
                    const int col = nt * 8 + cc;
                    const float2 bu2 = *reinterpret_cast<const float2*>(smp + OFF_BU + col);
                    const float2 r0v = *reinterpret_cast<const float2*>(
                        xsb + rr0 * XS_STRIDE + col);
                    const float2 r1v = *reinterpret_cast<const float2*>(
                        xsb + rr1 * XS_STRIDE + col);
                    float2 o0, o1;
                    o0.x = fmaf(0.1f, c0 + bu2.x, r0v.x);
                    o0.y = fmaf(0.1f, c1 + bu2.y, r0v.y);
                    o1.x = fmaf(0.1f, c2 + bu2.x, r1v.x);
                    o1.y = fmaf(0.1f, c3 + bu2.y, r1v.y);
                    *reinterpret_cast<float2*>(out + (rbase + rr0) * D_MODEL + col) = o0;
                    *reinterpret_cast<float2*>(out + (rbase + rr1) * D_MODEL + col) = o1;
                }
            }
            BAR_ARRIVE(B_EMP0 + bufc, NTHREADS); // x_s/dpart/stats[bufc] free
            b += GRID; s++;
        }
    }
}

extern "C" void kernel_launch(void* const* d_in, const int* in_sizes, int n_in,
                              void* d_out, int out_size)
{
    const float* x    = (const float*)d_in[0];
    const float* ln_g = (const float*)d_in[1];
    const float* ln_b = (const float*)d_in[2];
    const float* wd   = (const float*)d_in[3];
    const float* bd   = (const float*)d_in[4];
    const float* wu   = (const float*)d_in[5];
    const float* bu   = (const float*)d_in[6];
    float* out = (float*)d_out;

    cudaFuncSetAttribute(adapter_fused_kernel,
                         cudaFuncAttributeMaxDynamicSharedMemorySize, SMEM_BYTES);
    adapter_fused_kernel<<<GRID, NTHREADS, SMEM_BYTES>>>(x, ln_g, ln_b, wd, bd, wu, bu, out);
}